// round 5
// baseline (speedup 1.0000x reference)
#include <cuda_runtime.h>

#define HNUM 16
#define NSEQ 2048
#define DDIM 64
#define CHK  64                 // phase3 chunk
#define SUB  32                 // phase1 sub-chunk rows
#define NC   (NSEQ / CHK)       // 32 chunks / head
#define NSC  (NSEQ / SUB)       // 64 sub-chunks / head
#define NB   (HNUM * NC)        // 512 phase3 tiles
#define NBP  (HNUM * NSC)       // 1024 phase1 tiles
#define EPSV 1e-6f

#define ST 68                   // padded stride for transposed tiles / A

// Scratch
__device__ float g_KVp[(size_t)NBP * DDIM * DDIM];  // per-sub-chunk KV (16 MB)
__device__ float g_Kzp[(size_t)NBP * DDIM];         // per-sub-chunk K colsum
__device__ float g_S[(size_t)NB * DDIM * DDIM];     // exclusive prefix per chunk (8 MB)
__device__ float g_z[(size_t)NB * DDIM];            // exclusive prefix colsum

__device__ __forceinline__ float fmap(float x) {
    // elu(x) + 1 : x>0 -> x+1 ; x<=0 -> exp(x)
    return x > 0.f ? x + 1.f : __expf(x);
}

// ---------------------------------------------------------------------------
// Phase 1: per-SUB-chunk KV = phiK^T V (64x64) and Kz = colsum(phiK)
// grid = NBP (1024), block = 256, 4x4 register tiles (Round-2 proven config,
// halved per-CTA work to double CTAs/SM: occupancy fix for latency-boundness)
// ---------------------------------------------------------------------------
__global__ void __launch_bounds__(256) lin_phase1(const float* __restrict__ Kg,
                                                  const float* __restrict__ Vg) {
    __shared__ float sK[SUB * DDIM];    // 8 KB
    __shared__ float sV[SUB * DDIM];    // 8 KB
    const int tid = threadIdx.x;
    const size_t base = (size_t)blockIdx.x * (SUB * DDIM);

    #pragma unroll
    for (int s = 0; s < 2; s++) {
        int i4 = tid + s * 256;                 // 512 float4 per tensor
        float4 k = ((const float4*)(Kg + base))[i4];
        float4 v = ((const float4*)(Vg + base))[i4];
        k.x = fmap(k.x); k.y = fmap(k.y); k.z = fmap(k.z); k.w = fmap(k.w);
        ((float4*)sK)[i4] = k;
        ((float4*)sV)[i4] = v;
    }
    __syncthreads();

    const int d0 = (tid >> 4) * 4;
    const int e0 = (tid & 15) * 4;
    float acc[4][4] = {};
    #pragma unroll 8
    for (int m = 0; m < SUB; m++) {
        float4 kf = *(const float4*)&sK[m * DDIM + d0];
        float4 vf = *(const float4*)&sV[m * DDIM + e0];
        float kk[4] = {kf.x, kf.y, kf.z, kf.w};
        float vv[4] = {vf.x, vf.y, vf.z, vf.w};
        #pragma unroll
        for (int a = 0; a < 4; a++)
            #pragma unroll
            for (int b = 0; b < 4; b++)
                acc[a][b] += kk[a] * vv[b];
    }

    float* kvo = g_KVp + (size_t)blockIdx.x * (DDIM * DDIM);
    #pragma unroll
    for (int a = 0; a < 4; a++)
        *(float4*)&kvo[(d0 + a) * DDIM + e0] =
            make_float4(acc[a][0], acc[a][1], acc[a][2], acc[a][3]);

    if (tid < DDIM) {
        float s = 0.f;
        #pragma unroll 8
        for (int m = 0; m < SUB; m++) s += sK[m * DDIM + tid];
        g_Kzp[(size_t)blockIdx.x * DDIM + tid] = s;
    }
}

// ---------------------------------------------------------------------------
// Phase 2: scan 64 sub-chunk states per head (float4-wide); emit EXCLUSIVE
// prefix at each CHK (=2 sub-chunk) boundary into g_S / g_z.
// grid = 16 heads * 8 parts = 128, block = 128
// ---------------------------------------------------------------------------
__global__ void __launch_bounds__(128) lin_phase2() {
    const int h = blockIdx.x >> 3;
    const int part = blockIdx.x & 7;
    const int i4 = part * 128 + threadIdx.x;    // 0..1023 float4 index

    float4 run = make_float4(0.f, 0.f, 0.f, 0.f);
    #pragma unroll
    for (int sc = 0; sc < NSC; sc++) {
        if ((sc & 1) == 0)
            ((float4*)(g_S + ((size_t)h * NC + (sc >> 1)) * (DDIM * DDIM)))[i4] = run;
        float4 v = ((const float4*)(g_KVp + ((size_t)h * NSC + sc) * (DDIM * DDIM)))[i4];
        run.x += v.x; run.y += v.y; run.z += v.z; run.w += v.w;
    }
    if (part == 0 && threadIdx.x < DDIM / 4) {
        float4 rz = make_float4(0.f, 0.f, 0.f, 0.f);
        #pragma unroll
        for (int sc = 0; sc < NSC; sc++) {
            if ((sc & 1) == 0)
                ((float4*)(g_z + (size_t)(h * NC + (sc >> 1)) * DDIM))[threadIdx.x] = rz;
            float4 v = ((const float4*)(g_Kzp + (size_t)(h * NSC + sc) * DDIM))[threadIdx.x];
            rz.x += v.x; rz.y += v.y; rz.z += v.z; rz.w += v.w;
        }
    }
}

// ---------------------------------------------------------------------------
// Phase 3: per chunk (C=64)  [verbatim Round-2 structure: measured best]
//   A      = phiQ @ phiK^T   (64x64, causal-masked, stored TRANSPOSED)
//   den[m] = rowsum(A) + phiQ[m].z_excl + EPS
//   out    = (A @ V + phiQ @ S_excl) / den
// grid = NB (512), block = 256, 85.5 KB smem (2 CTAs/SM)
// ---------------------------------------------------------------------------
__global__ void __launch_bounds__(256) lin_phase3(const float* __restrict__ Qg,
                                                  const float* __restrict__ Kg,
                                                  const float* __restrict__ Vg,
                                                  float* __restrict__ Og) {
    extern __shared__ float sm[];
    float* sQt  = sm;                   // [d][m] DDIM*ST
    float* sKt  = sQt + DDIM * ST;      // [d][j] DDIM*ST
    float* sV   = sKt + DDIM * ST;      // [k][e] CHK*DDIM
    float* sS   = sV  + CHK * DDIM;     // [d][e] DDIM*DDIM
    float* sAt  = sS  + DDIM * DDIM;    // [k][m] CHK*ST (transposed, masked)
    float* sZ   = sAt + CHK * ST;       // DDIM
    float* sDen = sZ  + DDIM;           // CHK

    const int tid = threadIdx.x;
    const size_t base = (size_t)blockIdx.x * (CHK * DDIM);

    // --- load + feature map + transpose Q,K; V row-major; S,z from scratch ---
    {
        const int m  = tid >> 2;          // 0..63
        const int d0 = (tid & 3) * 16;    // 0,16,32,48
        #pragma unroll
        for (int u = 0; u < 4; u++) {
            int col = d0 + 4 * u;
            float4 q = *(const float4*)(Qg + base + m * DDIM + col);
            float4 k = *(const float4*)(Kg + base + m * DDIM + col);
            float4 v = *(const float4*)(Vg + base + m * DDIM + col);
            sQt[(col + 0) * ST + m] = fmap(q.x);
            sQt[(col + 1) * ST + m] = fmap(q.y);
            sQt[(col + 2) * ST + m] = fmap(q.z);
            sQt[(col + 3) * ST + m] = fmap(q.w);
            sKt[(col + 0) * ST + m] = fmap(k.x);
            sKt[(col + 1) * ST + m] = fmap(k.y);
            sKt[(col + 2) * ST + m] = fmap(k.z);
            sKt[(col + 3) * ST + m] = fmap(k.w);
            *(float4*)&sV[m * DDIM + col] = v;
        }
        const float4* Sg4 = (const float4*)(g_S + (size_t)blockIdx.x * (DDIM * DDIM));
        #pragma unroll
        for (int s = 0; s < 4; s++)
            ((float4*)sS)[tid + s * 256] = Sg4[tid + s * 256];
        if (tid < DDIM) sZ[tid] = g_z[(size_t)blockIdx.x * DDIM + tid];
    }
    __syncthreads();

    const int rbase = (tid >> 4) * 4;   // output rows (m)
    const int cbase = (tid & 15) * 4;   // output cols (j / e)

    // --- A-phase: A[m][j] = sum_d phiQ[m][d] phiK[j][d]; store transposed ---
    {
        float acc[4][4] = {};
        #pragma unroll 8
        for (int d = 0; d < DDIM; d++) {
            float4 qf = *(const float4*)&sQt[d * ST + rbase];
            float4 kf = *(const float4*)&sKt[d * ST + cbase];
            float qq[4] = {qf.x, qf.y, qf.z, qf.w};
            float kk[4] = {kf.x, kf.y, kf.z, kf.w};
            #pragma unroll
            for (int a = 0; a < 4; a++)
                #pragma unroll
                for (int b = 0; b < 4; b++)
                    acc[a][b] += qq[a] * kk[b];
        }
        #pragma unroll
        for (int b = 0; b < 4; b++) {
            int col = cbase + b;
            float4 o;
            o.x = (col <= rbase + 0) ? acc[0][b] : 0.f;
            o.y = (col <= rbase + 1) ? acc[1][b] : 0.f;
            o.z = (col <= rbase + 2) ? acc[2][b] : 0.f;
            o.w = (col <= rbase + 3) ? acc[3][b] : 0.f;
            *(float4*)&sAt[col * ST + rbase] = o;
        }
    }
    __syncthreads();

    // --- denominator ---
    if (tid < CHK) {
        float s = EPSV;
        #pragma unroll 8
        for (int k = 0; k < CHK; k++) s += sAt[k * ST + tid];
        #pragma unroll 8
        for (int d = 0; d < DDIM; d++) s += sQt[d * ST + tid] * sZ[d];
        sDen[tid] = 1.f / s;
    }
    __syncthreads();

    // --- B-phase: out = A@V + phiQ@S ---
    {
        float acc[4][4] = {};
        #pragma unroll 8
        for (int k = 0; k < CHK; k++) {
            float4 af = *(const float4*)&sAt[k * ST + rbase];
            float4 vf = *(const float4*)&sV[k * DDIM + cbase];
            float aa[4] = {af.x, af.y, af.z, af.w};
            float vv[4] = {vf.x, vf.y, vf.z, vf.w};
            #pragma unroll
            for (int a = 0; a < 4; a++)
                #pragma unroll
                for (int b = 0; b < 4; b++)
                    acc[a][b] += aa[a] * vv[b];
        }
        #pragma unroll 8
        for (int d = 0; d < DDIM; d++) {
            float4 qf = *(const float4*)&sQt[d * ST + rbase];
            float4 sf = *(const float4*)&sS[d * DDIM + cbase];
            float qq[4] = {qf.x, qf.y, qf.z, qf.w};
            float ss[4] = {sf.x, sf.y, sf.z, sf.w};
            #pragma unroll
            for (int a = 0; a < 4; a++)
                #pragma unroll
                for (int b = 0; b < 4; b++)
                    acc[a][b] += qq[a] * ss[b];
        }
        #pragma unroll
        for (int a = 0; a < 4; a++) {
            float inv = sDen[rbase + a];
            *(float4*)&Og[base + (size_t)(rbase + a) * DDIM + cbase] =
                make_float4(acc[a][0] * inv, acc[a][1] * inv,
                            acc[a][2] * inv, acc[a][3] * inv);
        }
    }
}

// ---------------------------------------------------------------------------
extern "C" void kernel_launch(void* const* d_in, const int* in_sizes, int n_in,
                              void* d_out, int out_size) {
    const float* Q = (const float*)d_in[0];
    const float* K = (const float*)d_in[1];
    const float* V = (const float*)d_in[2];
    float* O = (float*)d_out;

    const int SMEM3 = (2 * DDIM * ST + CHK * DDIM + DDIM * DDIM +
                       CHK * ST + DDIM + CHK) * (int)sizeof(float);   // ~85.5 KB

    static int inited = 0;
    if (!inited) {
        cudaFuncSetAttribute(lin_phase3, cudaFuncAttributeMaxDynamicSharedMemorySize, SMEM3);
        inited = 1;
    }

    lin_phase1<<<NBP, 256>>>(K, V);
    lin_phase2<<<HNUM * 8, 128>>>();
    lin_phase3<<<NB, 256, SMEM3>>>(Q, K, V, O);
}

// round 6
// speedup vs baseline: 1.3853x; 1.3853x over previous
#include <cuda_runtime.h>

#define HNUM 16
#define NSEQ 2048
#define DDIM 64
#define CHK  64
#define NC   (NSEQ / CHK)      // 32 chunks
#define NB   (HNUM * NC)       // 512 (head, chunk) tiles
#define EPSV 1e-6f

#define ST 68                  // padded stride for transposed tiles / A

// Scratch: per-(head,chunk) KV state (64x64) and K feature-sum (64).
// Phase 1 writes per-chunk sums; phase 2 converts in place to EXCLUSIVE prefix.
__device__ float g_KV[(size_t)NB * DDIM * DDIM];   // 8 MB
__device__ float g_Kz[(size_t)NB * DDIM];          // 128 KB

__device__ __forceinline__ float fmap(float x) {
    // elu(x) + 1 : x>0 -> x+1 ; x<=0 -> exp(x)
    return x > 0.f ? x + 1.f : __expf(x);
}

// ---------------------------------------------------------------------------
// Phase 1: per-chunk KV = phiK^T V  (64x64)  and Kz = colsum(phiK)
// grid = NB (512), block = 256   [verbatim R2 champion: measured 14.75us]
// ---------------------------------------------------------------------------
__global__ void __launch_bounds__(256) lin_phase1(const float* __restrict__ Kg,
                                                  const float* __restrict__ Vg) {
    extern __shared__ float sm[];
    float* sK = sm;                    // CHK*DDIM phiK (row-major)
    float* sV = sm + CHK * DDIM;       // CHK*DDIM
    const int tid = threadIdx.x;
    const size_t base = (size_t)blockIdx.x * (CHK * DDIM);

    #pragma unroll
    for (int s = 0; s < 4; s++) {
        int i4 = tid + s * 256;                 // float4 index, 1024 total
        float4 k = ((const float4*)(Kg + base))[i4];
        float4 v = ((const float4*)(Vg + base))[i4];
        k.x = fmap(k.x); k.y = fmap(k.y); k.z = fmap(k.z); k.w = fmap(k.w);
        ((float4*)sK)[i4] = k;
        ((float4*)sV)[i4] = v;
    }
    __syncthreads();

    const int d0 = (tid >> 4) * 4;
    const int e0 = (tid & 15) * 4;
    float acc[4][4] = {};
    #pragma unroll 8
    for (int m = 0; m < CHK; m++) {
        float4 kf = *(const float4*)&sK[m * DDIM + d0];
        float4 vf = *(const float4*)&sV[m * DDIM + e0];
        float kk[4] = {kf.x, kf.y, kf.z, kf.w};
        float vv[4] = {vf.x, vf.y, vf.z, vf.w};
        #pragma unroll
        for (int a = 0; a < 4; a++)
            #pragma unroll
            for (int b = 0; b < 4; b++)
                acc[a][b] += kk[a] * vv[b];
    }

    float* kvo = g_KV + (size_t)blockIdx.x * (DDIM * DDIM);
    #pragma unroll
    for (int a = 0; a < 4; a++)
        *(float4*)&kvo[(d0 + a) * DDIM + e0] =
            make_float4(acc[a][0], acc[a][1], acc[a][2], acc[a][3]);

    if (tid < DDIM) {
        float s = 0.f;
        #pragma unroll 8
        for (int m = 0; m < CHK; m++) s += sK[m * DDIM + tid];
        g_Kz[(size_t)blockIdx.x * DDIM + tid] = s;
    }
}

// ---------------------------------------------------------------------------
// Phase 2: in-place exclusive prefix over 32 chunks (per head).
// grid = 16 heads * 8 parts = 128, block = 512   [verbatim R2 champion]
// ---------------------------------------------------------------------------
__global__ void __launch_bounds__(512) lin_phase2() {
    const int h = blockIdx.x >> 3;
    const int part = blockIdx.x & 7;
    const int idx = part * 512 + threadIdx.x;   // 0..4095

    float run = 0.f;
    #pragma unroll
    for (int c = 0; c < NC; c++) {
        float* p = g_KV + ((size_t)(h * NC + c)) * (DDIM * DDIM) + idx;
        float v = *p;
        *p = run;
        run += v;
    }
    if (part == 0 && threadIdx.x < DDIM) {
        float rz = 0.f;
        #pragma unroll
        for (int c = 0; c < NC; c++) {
            float* p = g_Kz + (size_t)(h * NC + c) * DDIM + threadIdx.x;
            float v = *p;
            *p = rz;
            rz += v;
        }
    }
}

// ---------------------------------------------------------------------------
// Phase 3: per chunk (C=64):
//   A      = phiQ @ phiK^T   (64x64, causal-masked, stored TRANSPOSED)
//   den[m] = rowsum(A) + phiQ[m].z_excl + EPS
//   out    = (A @ V + phiQ @ S_excl) / den
// grid = NB (512), block = 256, 85.5 KB smem (2 CTAs/SM).
// B-phase uses balanced causal row-pairing: warp w owns rows {4w..4w+3} and
// {60-4w..63-4w}; A@V k-loop truncated in warp-uniform static segments.
// ---------------------------------------------------------------------------
__global__ void __launch_bounds__(256) lin_phase3(const float* __restrict__ Qg,
                                                  const float* __restrict__ Kg,
                                                  const float* __restrict__ Vg,
                                                  float* __restrict__ Og) {
    extern __shared__ float sm[];
    float* sQt  = sm;                   // [d][m] DDIM*ST
    float* sKt  = sQt + DDIM * ST;      // [d][j] DDIM*ST
    float* sV   = sKt + DDIM * ST;      // [k][e] CHK*DDIM
    float* sS   = sV  + CHK * DDIM;     // [d][e] DDIM*DDIM
    float* sAt  = sS  + DDIM * DDIM;    // [k][m] CHK*ST (transposed, masked)
    float* sZ   = sAt + CHK * ST;       // DDIM
    float* sDen = sZ  + DDIM;           // CHK

    const int tid = threadIdx.x;
    const size_t base = (size_t)blockIdx.x * (CHK * DDIM);

    // --- load + feature map + transpose Q,K; V row-major; S,z from scratch ---
    {
        const int m  = tid >> 2;          // 0..63
        const int d0 = (tid & 3) * 16;    // 0,16,32,48
        #pragma unroll
        for (int u = 0; u < 4; u++) {
            int col = d0 + 4 * u;
            float4 q = *(const float4*)(Qg + base + m * DDIM + col);
            float4 k = *(const float4*)(Kg + base + m * DDIM + col);
            float4 v = *(const float4*)(Vg + base + m * DDIM + col);
            sQt[(col + 0) * ST + m] = fmap(q.x);
            sQt[(col + 1) * ST + m] = fmap(q.y);
            sQt[(col + 2) * ST + m] = fmap(q.z);
            sQt[(col + 3) * ST + m] = fmap(q.w);
            sKt[(col + 0) * ST + m] = fmap(k.x);
            sKt[(col + 1) * ST + m] = fmap(k.y);
            sKt[(col + 2) * ST + m] = fmap(k.z);
            sKt[(col + 3) * ST + m] = fmap(k.w);
            *(float4*)&sV[m * DDIM + col] = v;
        }
        const float4* Sg4 = (const float4*)(g_KV + (size_t)blockIdx.x * (DDIM * DDIM));
        #pragma unroll
        for (int s = 0; s < 4; s++)
            ((float4*)sS)[tid + s * 256] = Sg4[tid + s * 256];
        if (tid < DDIM) sZ[tid] = g_Kz[(size_t)blockIdx.x * DDIM + tid];
    }
    __syncthreads();

    // --- A-phase: A[m][j] = sum_d phiQ[m][d] phiK[j][d]; store transposed ---
    {
        const int rbase = (tid >> 4) * 4;
        const int cbase = (tid & 15) * 4;
        float acc[4][4] = {};
        #pragma unroll 8
        for (int d = 0; d < DDIM; d++) {
            float4 qf = *(const float4*)&sQt[d * ST + rbase];
            float4 kf = *(const float4*)&sKt[d * ST + cbase];
            float qq[4] = {qf.x, qf.y, qf.z, qf.w};
            float kk[4] = {kf.x, kf.y, kf.z, kf.w};
            #pragma unroll
            for (int a = 0; a < 4; a++)
                #pragma unroll
                for (int b = 0; b < 4; b++)
                    acc[a][b] += qq[a] * kk[b];
        }
        #pragma unroll
        for (int b = 0; b < 4; b++) {
            int col = cbase + b;
            float4 o;
            o.x = (col <= rbase + 0) ? acc[0][b] : 0.f;
            o.y = (col <= rbase + 1) ? acc[1][b] : 0.f;
            o.z = (col <= rbase + 2) ? acc[2][b] : 0.f;
            o.w = (col <= rbase + 3) ? acc[3][b] : 0.f;
            *(float4*)&sAt[col * ST + rbase] = o;
        }
    }
    __syncthreads();

    // --- denominator ---
    if (tid < CHK) {
        float s = EPSV;
        #pragma unroll 8
        for (int k = 0; k < CHK; k++) s += sAt[k * ST + tid];
        #pragma unroll 8
        for (int d = 0; d < DDIM; d++) s += sQt[d * ST + tid] * sZ[d];
        sDen[tid] = 1.f / s;
    }
    __syncthreads();

    // --- B-phase: out = A@V + phiQ@S, balanced causal row-pairing ---
    {
        const int w    = tid >> 5;            // warp 0..7
        const int half = (tid >> 4) & 1;      // half-warp
        const int cb   = (tid & 15) * 4;      // output cols
        const int rL   = 4 * w + 2 * half;          // L rows rL, rL+1 (k < 4w+4)
        const int rH   = 60 - 4 * w + 2 * half;     // H rows rH, rH+1 (k < 64-4w)

        float accL[2][4] = {};
        float accH[2][4] = {};

        // A@V: 16 static segments of 4 k-steps, warp-uniform guards
        #pragma unroll
        for (int s = 0; s < 16; s++) {
            if (s < w + 1) {                       // both row-pairs live
                #pragma unroll
                for (int kk = 0; kk < 4; kk++) {
                    int k = s * 4 + kk;
                    float2 aL = *(const float2*)&sAt[k * ST + rL];
                    float2 aH = *(const float2*)&sAt[k * ST + rH];
                    float4 vf = *(const float4*)&sV[k * DDIM + cb];
                    float vv[4] = {vf.x, vf.y, vf.z, vf.w};
                    #pragma unroll
                    for (int b = 0; b < 4; b++) {
                        accL[0][b] += aL.x * vv[b];
                        accL[1][b] += aL.y * vv[b];
                        accH[0][b] += aH.x * vv[b];
                        accH[1][b] += aH.y * vv[b];
                    }
                }
            } else if (s < 16 - w) {               // only H row-pair live
                #pragma unroll
                for (int kk = 0; kk < 4; kk++) {
                    int k = s * 4 + kk;
                    float2 aH = *(const float2*)&sAt[k * ST + rH];
                    float4 vf = *(const float4*)&sV[k * DDIM + cb];
                    float vv[4] = {vf.x, vf.y, vf.z, vf.w};
                    #pragma unroll
                    for (int b = 0; b < 4; b++) {
                        accH[0][b] += aH.x * vv[b];
                        accH[1][b] += aH.y * vv[b];
                    }
                }
            }
        }

        // Q@S: full (no causal structure)
        #pragma unroll 8
        for (int d = 0; d < DDIM; d++) {
            float2 qL = *(const float2*)&sQt[d * ST + rL];
            float2 qH = *(const float2*)&sQt[d * ST + rH];
            float4 sf = *(const float4*)&sS[d * DDIM + cb];
            float ss[4] = {sf.x, sf.y, sf.z, sf.w};
            #pragma unroll
            for (int b = 0; b < 4; b++) {
                accL[0][b] += qL.x * ss[b];
                accL[1][b] += qL.y * ss[b];
                accH[0][b] += qH.x * ss[b];
                accH[1][b] += qH.y * ss[b];
            }
        }

        #pragma unroll
        for (int i = 0; i < 2; i++) {
            float invL = sDen[rL + i];
            *(float4*)&Og[base + (size_t)(rL + i) * DDIM + cb] =
                make_float4(accL[i][0] * invL, accL[i][1] * invL,
                            accL[i][2] * invL, accL[i][3] * invL);
            float invH = sDen[rH + i];
            *(float4*)&Og[base + (size_t)(rH + i) * DDIM + cb] =
                make_float4(accH[i][0] * invH, accH[i][1] * invH,
                            accH[i][2] * invH, accH[i][3] * invH);
        }
    }
}

// ---------------------------------------------------------------------------
extern "C" void kernel_launch(void* const* d_in, const int* in_sizes, int n_in,
                              void* d_out, int out_size) {
    const float* Q = (const float*)d_in[0];
    const float* K = (const float*)d_in[1];
    const float* V = (const float*)d_in[2];
    float* O = (float*)d_out;

    const int SMEM1 = 2 * CHK * DDIM * (int)sizeof(float);                   // 32 KB
    const int SMEM3 = (2 * DDIM * ST + CHK * DDIM + DDIM * DDIM +
                       CHK * ST + DDIM + CHK) * (int)sizeof(float);          // ~85.5 KB

    static int inited = 0;
    if (!inited) {
        cudaFuncSetAttribute(lin_phase1, cudaFuncAttributeMaxDynamicSharedMemorySize, SMEM1);
        cudaFuncSetAttribute(lin_phase3, cudaFuncAttributeMaxDynamicSharedMemorySize, SMEM3);
        inited = 1;
    }

    lin_phase1<<<NB, 256, SMEM1>>>(K, V);
    lin_phase2<<<HNUM * 8, 512>>>();
    lin_phase3<<<NB, 256, SMEM3>>>(Q, K, V, O);
}